// round 4
// baseline (speedup 1.0000x reference)
#include <cuda_runtime.h>
#include <cuda_bf16.h>
#include <cstdint>

// Problem constants
#define NBKG   100
#define NV1    50000
#define NTOT   60000
#define TLEN   1000
#define TPAD   1024      // padded T for restT, zero-filled tail
#define T_TILE 128       // timesteps per block (32 lanes x 4 t)
#define N_TILE 128       // neurons per block (4 phases x 32 neurons)
#define N_PHASE 32       // neurons staged per phase
#define OS_STRIDE 132    // staging row stride in floats (16B-aligned)

// Transposed bf16 copy of rest: restT[k][t], k in [0,100), t in [0,1024)
// Poisson counts are small integers -> exact in bf16.
__device__ __nv_bfloat16 g_restT[NBKG * TPAD];

// ---------------------------------------------------------------------------
// Prep: transpose + convert rest (1000 x 100 fp32) -> g_restT (100 x 1024 bf16)
// 32 blocks x 32 timesteps each (more parallelism -> lower latency).
// ---------------------------------------------------------------------------
#define TP 32
__global__ void __launch_bounds__(256) prep_kernel(const float* __restrict__ rest) {
    __shared__ float sh[TP][NBKG + 1];
    const int t0  = blockIdx.x * TP;
    const int tid = threadIdx.x;

    for (int idx = tid; idx < TP * NBKG; idx += 256) {
        int tt = idx / NBKG;
        int k  = idx - tt * NBKG;
        int t  = t0 + tt;
        sh[tt][k] = (t < TLEN) ? rest[t * NBKG + k] : 0.0f;
    }
    __syncthreads();

    for (int idx = tid; idx < TP * NBKG; idx += 256) {
        int k  = idx >> 5;        // idx / 32
        int tt = idx & 31;        // idx % 32
        g_restT[k * TPAD + t0 + tt] = __float2bfloat16(sh[tt][k]);
    }
}

// ---------------------------------------------------------------------------
// Main kernel: t-parallel gather (warp-uniform column index -> conflict-free,
// vectorized bf16x4 loads, L1-resident), fp32 accumulate, small smem-staged
// transpose (4 phases of 32 neurons -> 16.9KB smem -> 8 CTAs/SM), then
// n-coalesced 128B-line STG writeback.
// ---------------------------------------------------------------------------
__global__ void __launch_bounds__(256, 8) noise_kernel(
    const float* __restrict__ v1_w, const int* __restrict__ v1_c,
    const float* __restrict__ lm_w, const int* __restrict__ lm_c,
    float* __restrict__ out)
{
    __shared__ float out_s[N_PHASE * OS_STRIDE];   // 16,896 B

    const int tid  = threadIdx.x;
    const int lane = tid & 31;
    const int wrp  = tid >> 5;                 // 8 warps
    const int nb   = blockIdx.x * N_TILE;      // neuron tile base
    const int t0   = blockIdx.y * T_TILE;      // timestep tile base
    const int tofs = t0 + 4 * lane;            // this lane's 4 timesteps
    const __nv_bfloat16* __restrict__ rT = g_restT;

    #pragma unroll 1
    for (int ph = 0; ph < N_TILE / N_PHASE; ph++) {
        // ---- compute: each warp handles 4 consecutive neurons this phase ----
        #pragma unroll
        for (int i = 0; i < 4; i++) {
            const int nl = ph * N_PHASE + wrp * 4 + i;   // local neuron [0,128)
            const int n  = nb + nl;                      // global neuron
            if (n < NTOT) {                              // warp-uniform
                const float* wp;
                const int*   cp;
                if (n < NV1) { wp = v1_w + 4 * n;          cp = v1_c + 4 * n; }
                else         { wp = lm_w + 4 * (n - NV1);  cp = lm_c + 4 * (n - NV1); }

                const float4 wv = *reinterpret_cast<const float4*>(wp);  // uniform
                const int4   cv = *reinterpret_cast<const int4*>(cp);    // uniform

                float a0, a1, a2, a3;
                {
                    uint2 v = *reinterpret_cast<const uint2*>(&rT[cv.x * TPAD + tofs]);
                    a0 = wv.x * __uint_as_float(v.x << 16);
                    a1 = wv.x * __uint_as_float(v.x & 0xFFFF0000u);
                    a2 = wv.x * __uint_as_float(v.y << 16);
                    a3 = wv.x * __uint_as_float(v.y & 0xFFFF0000u);
                }
                {
                    uint2 v = *reinterpret_cast<const uint2*>(&rT[cv.y * TPAD + tofs]);
                    a0 += wv.y * __uint_as_float(v.x << 16);
                    a1 += wv.y * __uint_as_float(v.x & 0xFFFF0000u);
                    a2 += wv.y * __uint_as_float(v.y << 16);
                    a3 += wv.y * __uint_as_float(v.y & 0xFFFF0000u);
                }
                {
                    uint2 v = *reinterpret_cast<const uint2*>(&rT[cv.z * TPAD + tofs]);
                    a0 += wv.z * __uint_as_float(v.x << 16);
                    a1 += wv.z * __uint_as_float(v.x & 0xFFFF0000u);
                    a2 += wv.z * __uint_as_float(v.y << 16);
                    a3 += wv.z * __uint_as_float(v.y & 0xFFFF0000u);
                }
                {
                    uint2 v = *reinterpret_cast<const uint2*>(&rT[cv.w * TPAD + tofs]);
                    a0 += wv.w * __uint_as_float(v.x << 16);
                    a1 += wv.w * __uint_as_float(v.x & 0xFFFF0000u);
                    a2 += wv.w * __uint_as_float(v.y << 16);
                    a3 += wv.w * __uint_as_float(v.y & 0xFFFF0000u);
                }

                // STS.128: uniform row, lanes consecutive 16B -> conflict-free
                *reinterpret_cast<float4*>(&out_s[(nl & 31) * OS_STRIDE + 4 * lane]) =
                    make_float4(a0, a1, a2, a3);
            }
        }

        __syncthreads();

        // ---- writeback: lanes map to 32 consecutive neurons -> 128B STG lines ----
        {
            const int n = nb + ph * N_PHASE + lane;      // global neuron
            if (n < NTOT) {
                float* orow = out + n;
                #pragma unroll
                for (int j = 0; j < 4; j++) {
                    const int q = wrp + 8 * j;           // t-quad index [0,32)
                    const int t = t0 + 4 * q;
                    if (t < TLEN) {                      // TLEN%4==0 -> exact guard
                        float4 v = *reinterpret_cast<const float4*>(
                            &out_s[lane * OS_STRIDE + 4 * q]);
                        orow[(size_t)(t + 0) * NTOT] = v.x;
                        orow[(size_t)(t + 1) * NTOT] = v.y;
                        orow[(size_t)(t + 2) * NTOT] = v.z;
                        orow[(size_t)(t + 3) * NTOT] = v.w;
                    }
                }
            }
        }

        __syncthreads();
    }
}

// ---------------------------------------------------------------------------
// Launch. Inputs (metadata order):
//   0: rest        (100000 f32)   [1000 x 100]
//   1: v1_weights  (200000 f32)
//   2: v1_rows     (unused: rows == repeat(arange(NV1), 4))
//   3: v1_cols     (200000 i32)
//   4: lm_weights  (40000 f32)
//   5: lm_rows     (unused)
//   6: lm_cols     (40000 i32)
// Output: 60,000,000 f32, out[t*60000 + n].
// ---------------------------------------------------------------------------
extern "C" void kernel_launch(void* const* d_in, const int* in_sizes, int n_in,
                              void* d_out, int out_size) {
    const float* rest = (const float*)d_in[0];
    const float* v1_w = (const float*)d_in[1];
    const int*   v1_c = (const int*)  d_in[3];
    const float* lm_w = (const float*)d_in[4];
    const int*   lm_c = (const int*)  d_in[6];
    float*       out  = (float*)d_out;

    prep_kernel<<<TPAD / TP, 256>>>(rest);     // 32 blocks

    dim3 grid((NTOT + N_TILE - 1) / N_TILE,    // 469 neuron tiles (x fastest:
              (TLEN + T_TILE - 1) / T_TILE);   //  co-resident blocks share t-tile)
    noise_kernel<<<grid, 256>>>(v1_w, v1_c, lm_w, lm_c, out);
}

// round 12
// speedup vs baseline: 1.6153x; 1.6153x over previous
#include <cuda_runtime.h>
#include <cuda_bf16.h>
#include <cstdint>

// Problem constants
#define NBKG    100
#define NV1     50000
#define NTOT    60000
#define TLEN    1000
#define TPAD    1024     // padded T for restT, zero-filled tail
#define T_TILE  128      // timesteps per block (32 lanes x 4 t)
#define N_TILE  256      // neurons per block (8 phases x 32 neurons)
#define N_PHASE 32       // neurons staged per phase

// Transposed bf16 copy of rest: restT[k][t], k in [0,100), t in [0,1024)
// Poisson counts are small integers -> exact in bf16.
__device__ __nv_bfloat16 g_restT[NBKG * TPAD];

// ---------------------------------------------------------------------------
// Prep: transpose + convert rest (1000 x 100 fp32) -> g_restT (100 x 1024 bf16)
// ---------------------------------------------------------------------------
#define TP 32
__global__ void __launch_bounds__(256) prep_kernel(const float* __restrict__ rest) {
    __shared__ float sh[TP][NBKG + 1];
    const int t0  = blockIdx.x * TP;
    const int tid = threadIdx.x;

    for (int idx = tid; idx < TP * NBKG; idx += 256) {
        int tt = idx / NBKG;
        int k  = idx - tt * NBKG;
        int t  = t0 + tt;
        sh[tt][k] = (t < TLEN) ? rest[t * NBKG + k] : 0.0f;
    }
    __syncthreads();

    for (int idx = tid; idx < TP * NBKG; idx += 256) {
        int k  = idx >> 5;        // idx / 32
        int tt = idx & 31;        // idx % 32
        g_restT[k * TPAD + t0 + tt] = __float2bfloat16(sh[tt][k]);
    }
}

// ---------------------------------------------------------------------------
// Main kernel. Key structure:
//  - block's 100 x 128 bf16 rest slice copied ONCE to smem (amortized over
//    256 neurons) -> gathers are uniform-row LDS.64, off the L1-global path
//  - XOR-swizzled staging tile (chunk ^= row): conflict-free STS.128 row
//    writes AND conflict-free LDS.128 column reads
//  - n-coalesced STG.32 writeback (1 wavefront per 128B line)
// ---------------------------------------------------------------------------
__global__ void __launch_bounds__(256) noise_kernel(
    const float* __restrict__ v1_w, const int* __restrict__ v1_c,
    const float* __restrict__ lm_w, const int* __restrict__ lm_c,
    float* __restrict__ out)
{
    __shared__ __nv_bfloat16 rest_s[NBKG * T_TILE];   // 25,600 B  [k][t]
    __shared__ float out_s[N_PHASE * T_TILE];         // 16,384 B  swizzled

    const int tid  = threadIdx.x;
    const int lane = tid & 31;
    const int wrp  = tid >> 5;                 // 8 warps
    const int nb   = blockIdx.x * N_TILE;      // neuron tile base
    const int t0   = blockIdx.y * T_TILE;      // timestep tile base

    // ---- copy rest slice: g_restT[k][t0 .. t0+127] -> rest_s[k][0..127] ----
    {
        const uint4* src = reinterpret_cast<const uint4*>(&g_restT[t0]);
        uint4*       dst = reinterpret_cast<uint4*>(rest_s);
        // row = 128 bf16 = 256B = 16 uint4; 100 rows = 1600 uint4
        #pragma unroll 1
        for (int i = tid; i < NBKG * 16; i += 256) {
            int k = i >> 4;
            int c = i & 15;
            dst[i] = src[k * (TPAD / 8) + c];   // TPAD bf16 = TPAD/8 uint4
        }
    }
    __syncthreads();

    #pragma unroll 1
    for (int ph = 0; ph < N_TILE / N_PHASE; ph++) {
        // ---- compute: each warp handles 4 consecutive neurons this phase ----
        #pragma unroll
        for (int i = 0; i < 4; i++) {
            const int r  = wrp * 4 + i;                  // staging row [0,32)
            const int n  = nb + ph * N_PHASE + r;        // global neuron
            if (n < NTOT) {                              // warp-uniform
                const float* wp;
                const int*   cp;
                if (n < NV1) { wp = v1_w + 4 * n;          cp = v1_c + 4 * n; }
                else         { wp = lm_w + 4 * (n - NV1);  cp = lm_c + 4 * (n - NV1); }

                const float4 wv = *reinterpret_cast<const float4*>(wp);  // uniform
                const int4   cv = *reinterpret_cast<const int4*>(cp);    // uniform

                float a0, a1, a2, a3;
                // uniform-row smem gathers: lanes cover 8B each, conflict-free
                {
                    uint2 v = *reinterpret_cast<const uint2*>(&rest_s[cv.x * T_TILE + 4 * lane]);
                    a0 = wv.x * __uint_as_float(v.x << 16);
                    a1 = wv.x * __uint_as_float(v.x & 0xFFFF0000u);
                    a2 = wv.x * __uint_as_float(v.y << 16);
                    a3 = wv.x * __uint_as_float(v.y & 0xFFFF0000u);
                }
                {
                    uint2 v = *reinterpret_cast<const uint2*>(&rest_s[cv.y * T_TILE + 4 * lane]);
                    a0 += wv.y * __uint_as_float(v.x << 16);
                    a1 += wv.y * __uint_as_float(v.x & 0xFFFF0000u);
                    a2 += wv.y * __uint_as_float(v.y << 16);
                    a3 += wv.y * __uint_as_float(v.y & 0xFFFF0000u);
                }
                {
                    uint2 v = *reinterpret_cast<const uint2*>(&rest_s[cv.z * T_TILE + 4 * lane]);
                    a0 += wv.z * __uint_as_float(v.x << 16);
                    a1 += wv.z * __uint_as_float(v.x & 0xFFFF0000u);
                    a2 += wv.z * __uint_as_float(v.y << 16);
                    a3 += wv.z * __uint_as_float(v.y & 0xFFFF0000u);
                }
                {
                    uint2 v = *reinterpret_cast<const uint2*>(&rest_s[cv.w * T_TILE + 4 * lane]);
                    a0 += wv.w * __uint_as_float(v.x << 16);
                    a1 += wv.w * __uint_as_float(v.x & 0xFFFF0000u);
                    a2 += wv.w * __uint_as_float(v.y << 16);
                    a3 += wv.w * __uint_as_float(v.y & 0xFFFF0000u);
                }

                // STS.128 to row r, t-quad = lane, physical chunk = lane ^ r
                // -> lanes hit distinct 16B chunks: conflict-free
                *reinterpret_cast<float4*>(&out_s[r * T_TILE + ((lane ^ r) << 2)]) =
                    make_float4(a0, a1, a2, a3);
            }
        }

        __syncthreads();

        // ---- writeback: lane = neuron (32 consecutive) -> 128B STG lines ----
        {
            const int n = nb + ph * N_PHASE + lane;      // global neuron
            if (n < NTOT) {
                float* orow = out + n;
                #pragma unroll
                for (int j = 0; j < 4; j++) {
                    const int q = wrp + 8 * j;           // t-quad index [0,32)
                    const int t = t0 + 4 * q;
                    if (t < TLEN) {                      // TLEN%4==0 -> exact guard
                        // LDS.128 row = lane, chunk = q ^ lane: conflict-free
                        float4 v = *reinterpret_cast<const float4*>(
                            &out_s[lane * T_TILE + ((q ^ lane) << 2)]);
                        orow[(size_t)(t + 0) * NTOT] = v.x;
                        orow[(size_t)(t + 1) * NTOT] = v.y;
                        orow[(size_t)(t + 2) * NTOT] = v.z;
                        orow[(size_t)(t + 3) * NTOT] = v.w;
                    }
                }
            }
        }

        __syncthreads();
    }
}

// ---------------------------------------------------------------------------
// Launch. Inputs (metadata order):
//   0: rest        (100000 f32)   [1000 x 100]
//   1: v1_weights  (200000 f32)
//   2: v1_rows     (unused: rows == repeat(arange(NV1), 4))
//   3: v1_cols     (200000 i32)
//   4: lm_weights  (40000 f32)
//   5: lm_rows     (unused)
//   6: lm_cols     (40000 i32)
// Output: 60,000,000 f32, out[t*60000 + n].
// ---------------------------------------------------------------------------
extern "C" void kernel_launch(void* const* d_in, const int* in_sizes, int n_in,
                              void* d_out, int out_size) {
    const float* rest = (const float*)d_in[0];
    const float* v1_w = (const float*)d_in[1];
    const int*   v1_c = (const int*)  d_in[3];
    const float* lm_w = (const float*)d_in[4];
    const int*   lm_c = (const int*)  d_in[6];
    float*       out  = (float*)d_out;

    prep_kernel<<<TPAD / TP, 256>>>(rest);     // 32 blocks

    dim3 grid((NTOT + N_TILE - 1) / N_TILE,    // 235 neuron tiles
              (TLEN + T_TILE - 1) / T_TILE);   // 8 t-tiles
    noise_kernel<<<grid, 256>>>(v1_w, v1_c, lm_w, lm_c, out);
}